// round 16
// baseline (speedup 1.0000x reference)
#include <cuda_runtime.h>
#include <cuda_bf16.h>
#include <cstdint>

#define BD 4
#define TD 50
#define DD 512
#define SRCN 400
#define SENTN 16
#define WORDN 40
#define SJ 1040
#define BT 200

#define MROWS 5120
#define ROW_SENT 0
#define ROW_SRC 128
#define ROW_WORD 1792
#define ROW_WQW 4352
#define ROW_WQS 4608
#define ROW_WQP 4864

// ---- scratch (device globals) ----
__device__ __nv_bfloat16 g_AhiG[MROWS * DD];
__device__ __nv_bfloat16 g_AloG[MROWS * DD];
__device__ __nv_bfloat16 g_BhG[6 * DD * DD];   // [set][k][n]
__device__ __nv_bfloat16 g_BlG[6 * DD * DD];
__device__ float g_act[MROWS * DD];
__device__ float g_sent[BT * SENTN];
__device__ float g_alignQ[4 * BT * SJ];        // d-quarter partial scores
__device__ float g_p[BT * SJ];

__device__ __forceinline__ float tanh_fast(float x) {
    float y;
    asm("tanh.approx.f32 %0, %1;" : "=f"(y) : "f"(x));
    return y;
}
__device__ __forceinline__ uint32_t smem_u32(const void* p) {
    uint32_t a;
    asm("{ .reg .u64 t; cvta.to.shared.u64 t, %1; cvt.u32.u64 %0, t; }" : "=r"(a) : "l"(p));
    return a;
}
#define MMA_BF16(d, a, b) \
    asm volatile("mma.sync.aligned.m16n8k16.row.col.f32.bf16.bf16.f32 " \
        "{%0,%1,%2,%3}, {%4,%5,%6,%7}, {%8,%9}, {%0,%1,%2,%3};" \
        : "+f"((d)[0]), "+f"((d)[1]), "+f"((d)[2]), "+f"((d)[3]) \
        : "r"((a)[0]), "r"((a)[1]), "r"((a)[2]), "r"((a)[3]), "r"((b)[0]), "r"((b)[1]))
#define LDSM_X4_T(r, addr) \
    asm volatile("ldmatrix.sync.aligned.m8n8.x4.trans.shared.b16 {%0,%1,%2,%3}, [%4];" \
        : "=r"((r)[0]), "=r"((r)[1]), "=r"((r)[2]), "=r"((r)[3]) : "r"(addr))
#define CP_ASYNC16(saddr, gptr) \
    asm volatile("cp.async.cg.shared.global [%0], [%1], 16;" :: "r"(saddr), "l"(gptr))
#define CP_COMMIT() asm volatile("cp.async.commit_group;" ::: "memory")
#define CP_WAIT1()  asm volatile("cp.async.wait_group 1;" ::: "memory")
#define CP_WAIT0()  asm volatile("cp.async.wait_group 0;" ::: "memory")

__device__ __forceinline__ uint32_t pack_bf2(float a, float b) {
    __nv_bfloat162 t = __floats2bfloat162_rn(a, b);
    return *(uint32_t*)&t;
}

// ============================================================
// merged conversion: blocks [0,MROWS) gather+split A rows;
// blocks [MROWS, MROWS+3072) split the 6 weight matrices.
// ============================================================
__global__ __launch_bounds__(128) void conv_ab(
    const float* __restrict__ sentb, const float* __restrict__ srcb,
    const float* __restrict__ wordb, const float* __restrict__ source,
    const float* __restrict__ W0, const float* __restrict__ W1, const float* __restrict__ W2,
    const float* __restrict__ W3, const float* __restrict__ W4, const float* __restrict__ W5)
{
    int blk = blockIdx.x;
    if (blk < MROWS) {
        int r = blk;
        const float* p;
        if (r < ROW_SRC) {
            int q = r < 64 ? r : 63; int b = q >> 4, j = q & 15;
            p = sentb + (size_t)(j * BD + b) * DD;
        } else if (r < ROW_WORD) {
            int q = r - ROW_SRC; if (q > 1599) q = 1599;
            int b = q / SRCN, i = q - b * SRCN;
            p = srcb + (size_t)(i * BD + b) * DD;
        } else if (r < ROW_WQW) {
            int q = r - ROW_WORD; int b = q / 640, rem = q - b * 640;
            int s = rem / WORDN, w = rem - s * WORDN;
            p = wordb + (size_t)((w * BD + b) * SENTN + s) * DD;
        } else {
            int q = (r - ROW_WQW) & 255; if (q > BT - 1) q = BT - 1;
            p = source + (size_t)q * DD;
        }
        int d = threadIdx.x * 4;
        float4 x = *(const float4*)(p + d);
        __nv_bfloat162 h01 = __floats2bfloat162_rn(x.x, x.y);
        __nv_bfloat162 h23 = __floats2bfloat162_rn(x.z, x.w);
        float l0 = x.x - __low2float(h01), l1 = x.y - __high2float(h01);
        float l2 = x.z - __low2float(h23), l3 = x.w - __high2float(h23);
        size_t o = (size_t)r * DD + d;
        *(uint2*)&g_AhiG[o] = make_uint2(*(uint32_t*)&h01, *(uint32_t*)&h23);
        *(uint2*)&g_AloG[o] = make_uint2(pack_bf2(l0, l1), pack_bf2(l2, l3));
    } else {
        int g = blk - MROWS;
        int set = g >> 9, k = g & 511;
        const float* W = (set == 0) ? W0 : (set == 1) ? W1 : (set == 2) ? W2 :
                         (set == 3) ? W3 : (set == 4) ? W4 : W5;
        int n = threadIdx.x * 4;
        float4 x = *(const float4*)&W[(size_t)k * DD + n];
        __nv_bfloat162 h01 = __floats2bfloat162_rn(x.x, x.y);
        __nv_bfloat162 h23 = __floats2bfloat162_rn(x.z, x.w);
        float l0 = x.x - __low2float(h01), l1 = x.y - __high2float(h01);
        float l2 = x.z - __low2float(h23), l3 = x.w - __high2float(h23);
        size_t o = (size_t)set * DD * DD + (size_t)k * DD + n;
        *(uint2*)&g_BhG[o] = make_uint2(*(uint32_t*)&h01, *(uint32_t*)&h23);
        *(uint2*)&g_BlG[o] = make_uint2(pack_bf2(l0, l1), pack_bf2(l2, l3));
    }
}

// ============================================================
// split-bf16 (3-pass) mma GEMM, cp.async 2-stage pipeline
// CTA tile 64(M) x 64(N), K=512, 128 threads (4 warps, warp tile 32x32)
// grid (80, 8) = 640 CTAs (~4.3/SM, single wave, tail 1.25x)
// static smem: Ahi[2][64*20]u32 | Alo[2] | Bh[2][32*36]u32 | Bl[2] = 38 KB
// ============================================================
#define APST 20
#define BST_U 36
#define BSTH 72
#define A_ST (64 * APST)
#define B_ST (32 * BST_U)
#define OFF_AHI(s) ((s) * A_ST)
#define OFF_ALO(s) (2 * A_ST + (s) * A_ST)
#define OFF_BH(s)  (4 * A_ST + (s) * B_ST)
#define OFF_BL(s)  (4 * A_ST + 2 * B_ST + (s) * B_ST)
#define SMEM_U     (4 * A_ST + 4 * B_ST)

__device__ __forceinline__ void stage_chunk64(
    uint32_t sb, int st, int kc, int m0, int n0,
    const __nv_bfloat16* BhSeg, const __nv_bfloat16* BlSeg, int tid)
{
    int k0 = kc * 32;
    // A: 64 rows x 32 k halves = 256 granules of 16B per matrix
#pragma unroll
    for (int s = 0; s < 2; s++) {
        int g = tid + s * 128;
        int row = g >> 2, c = g & 3;             // c*8 halves
        size_t go = (size_t)(m0 + row) * DD + k0 + c * 8;
        uint32_t so = 4 * (uint32_t)(row * APST + c * 4);
        CP_ASYNC16(sb + 4 * OFF_AHI(st) + so, g_AhiG + go);
        CP_ASYNC16(sb + 4 * OFF_ALO(st) + so, g_AloG + go);
    }
    // B: 32 k x 64 n halves = 256 granules per matrix
#pragma unroll
    for (int s = 0; s < 2; s++) {
        int g = tid + s * 128;
        int k = g >> 3, c = g & 7;               // c*8 halves
        size_t go = (size_t)(k0 + k) * DD + n0 + c * 8;
        uint32_t so = 4 * (uint32_t)(k * BST_U + c * 4);
        CP_ASYNC16(sb + 4 * OFF_BH(st) + so, BhSeg + go);
        CP_ASYNC16(sb + 4 * OFF_BL(st) + so, BlSeg + go);
    }
}

__global__ __launch_bounds__(128, 5) void bf16_gemm(
    const float* __restrict__ bqw, const float* __restrict__ bqs, const float* __restrict__ bqp)
{
    __shared__ __align__(16) uint32_t smU[SMEM_U];
    uint32_t sb = smem_u32(smU);

    int tid = threadIdx.x, lane = tid & 31, wid = tid >> 5;
    int m0 = blockIdx.x * 64, n0 = blockIdx.y * 64;
    int seg = (m0 < ROW_SRC) ? 0 : (m0 < ROW_WORD) ? 1 : (m0 < ROW_WQW) ? 2 :
              (m0 < ROW_WQS) ? 3 : (m0 < ROW_WQP) ? 4 : 5;
    const __nv_bfloat16* BhSeg = g_BhG + (size_t)seg * DD * DD;
    const __nv_bfloat16* BlSeg = g_BlG + (size_t)seg * DD * DD;

    int wm = (wid & 1) * 32, wn = (wid >> 1) * 32;
    int gr = lane >> 2, gc = lane & 3;
    int quad = lane >> 3, lrow = lane & 7;
    int ldsm_half = ((quad & 1) * 8 + lrow) * BSTH + (quad >> 1) * 8 + wn;

    float acc[2][4][4];
#pragma unroll
    for (int mt = 0; mt < 2; mt++)
#pragma unroll
        for (int nt = 0; nt < 4; nt++)
#pragma unroll
            for (int c = 0; c < 4; c++) acc[mt][nt][c] = 0.0f;

    stage_chunk64(sb, 0, 0, m0, n0, BhSeg, BlSeg, tid);
    CP_COMMIT();

    for (int kc = 0; kc < 16; kc++) {
        int st = kc & 1;
        if (kc < 15) {
            stage_chunk64(sb, st ^ 1, kc + 1, m0, n0, BhSeg, BlSeg, tid);
            CP_COMMIT();
            CP_WAIT1();
        } else {
            CP_WAIT0();
        }
        __syncthreads();

#pragma unroll
        for (int step = 0; step < 2; step++) {
            int kkp = step * 8;       // A pair offset (u32)
            int kk2 = step * 16;      // B k-row offset
            uint32_t ah[2][4], al[2][4];
#pragma unroll
            for (int mt = 0; mt < 2; mt++) {
                int mr = wm + mt * 16 + gr;
                ah[mt][0] = smU[OFF_AHI(st) + mr * APST + kkp + gc];
                ah[mt][1] = smU[OFF_AHI(st) + (mr + 8) * APST + kkp + gc];
                ah[mt][2] = smU[OFF_AHI(st) + mr * APST + kkp + gc + 4];
                ah[mt][3] = smU[OFF_AHI(st) + (mr + 8) * APST + kkp + gc + 4];
                al[mt][0] = smU[OFF_ALO(st) + mr * APST + kkp + gc];
                al[mt][1] = smU[OFF_ALO(st) + (mr + 8) * APST + kkp + gc];
                al[mt][2] = smU[OFF_ALO(st) + mr * APST + kkp + gc + 4];
                al[mt][3] = smU[OFF_ALO(st) + (mr + 8) * APST + kkp + gc + 4];
            }
#pragma unroll
            for (int np = 0; np < 2; np++) {
                uint32_t hoff = (uint32_t)((kk2 * BSTH + np * 16 + ldsm_half) * 2);
                uint32_t bh4[4], bl4[4];
                LDSM_X4_T(bh4, sb + 4 * OFF_BH(st) + hoff);
                LDSM_X4_T(bl4, sb + 4 * OFF_BL(st) + hoff);
#pragma unroll
                for (int sub = 0; sub < 2; sub++) {
#pragma unroll
                    for (int mt = 0; mt < 2; mt++) {
                        MMA_BF16(acc[mt][np * 2 + sub], ah[mt], &bh4[sub * 2]);
                        MMA_BF16(acc[mt][np * 2 + sub], ah[mt], &bl4[sub * 2]);
                        MMA_BF16(acc[mt][np * 2 + sub], al[mt], &bh4[sub * 2]);
                    }
                }
            }
        }
        __syncthreads();
    }

    const float* bias = (seg == 3) ? bqw : (seg == 4) ? bqs : (seg == 5) ? bqp : (const float*)0;
#pragma unroll
    for (int nt = 0; nt < 4; nt++) {
        int n = n0 + wn + nt * 8 + gc * 2;
        float b0 = bias ? bias[n] : 0.0f;
        float b1 = bias ? bias[n + 1] : 0.0f;
#pragma unroll
        for (int mt = 0; mt < 2; mt++) {
            int m = m0 + wm + mt * 16 + gr;
            *(float2*)&g_act[(size_t)m * DD + n] =
                make_float2(acc[mt][nt][0] + b0, acc[mt][nt][1] + b1);
            *(float2*)&g_act[(size_t)(m + 8) * DD + n] =
                make_float2(acc[mt][nt][2] + b0, acc[mt][nt][3] + b1);
        }
    }
}

// ============================================================
// sentence-level scores
// ============================================================
__global__ __launch_bounds__(512) void sent_kernel(const float* __restrict__ v_sent)
{
    __shared__ float wq_s[DD];
    __shared__ float vs[DD];
    int row = blockIdx.x;
    int b = row / TD;
    int tid = threadIdx.x, lane = tid & 31, w = tid >> 5;
    wq_s[tid] = g_act[(size_t)(ROW_WQS + row) * DD + tid];
    vs[tid] = v_sent[tid];
    __syncthreads();
    const float* uh = g_act + (size_t)(b * 16 + w) * DD;
    float acc = 0.f;
#pragma unroll
    for (int it = 0; it < 4; it++) {
        int d = it * 128 + lane * 4;
        float4 u = *(const float4*)&uh[d];
        acc += vs[d + 0] * tanh_fast(wq_s[d + 0] + u.x);
        acc += vs[d + 1] * tanh_fast(wq_s[d + 1] + u.y);
        acc += vs[d + 2] * tanh_fast(wq_s[d + 2] + u.z);
        acc += vs[d + 3] * tanh_fast(wq_s[d + 3] + u.w);
    }
#pragma unroll
    for (int o = 16; o; o >>= 1) acc += __shfl_xor_sync(0xffffffffu, acc, o);
    if (lane == 0) g_sent[row * SENTN + w] = acc;
}

// ============================================================
// main score kernel: d split in QUARTERS (grid z = b + 4*q, 16)
// ============================================================
#define SC_CHUNK 64
#define SC_STRIDE 68
__global__ __launch_bounds__(256) void score_kernel(
    const float* __restrict__ v_pass, const float* __restrict__ v_word)
{
    __shared__ float wq_s[16 * SC_STRIDE];
    __shared__ float uh_s[80 * SC_STRIDE];
    __shared__ float v_s[SC_CHUNK];
    int tid = threadIdx.x;
    int jt = blockIdx.x, tt = blockIdx.y;
    int b = blockIdx.z & 3, quar = blockIdx.z >> 2;
    int t0 = tt * 16;
    bool is_src = (jt < 5);
    const float* wqb = g_act + (size_t)((is_src ? ROW_WQP : ROW_WQW) + b * TD) * DD;
    int uh0 = is_src ? (ROW_SRC + b * SRCN + jt * 80) : (ROW_WORD + b * 640 + (jt - 5) * 80);
    const float* v = is_src ? v_pass : v_word;
    int d_base = quar * 128;

    int tx = tid & 15, ty = tid >> 4;
    float acc[5] = {0.f, 0.f, 0.f, 0.f, 0.f};

    for (int c = 0; c < 2; c++) {
        int d0 = d_base + c * SC_CHUNK;
        __syncthreads();
        {
            int r = tid >> 4, col = (tid & 15) << 2;
            *(float4*)&wq_s[r * SC_STRIDE + col] =
                *(const float4*)&wqb[(size_t)(t0 + r) * DD + d0 + col];
        }
        for (int i = tid; i < 80 * 16; i += 256) {
            int r = i >> 4, col = (i & 15) << 2;
            *(float4*)&uh_s[r * SC_STRIDE + col] =
                *(const float4*)&g_act[(size_t)(uh0 + r) * DD + d0 + col];
        }
        if (tid < SC_CHUNK) v_s[tid] = v[d0 + tid];
        __syncthreads();
#pragma unroll 4
        for (int d4 = 0; d4 < 16; d4++) {
            float4 w4 = *(const float4*)&wq_s[ty * SC_STRIDE + (d4 << 2)];
            float4 v4 = *(const float4*)&v_s[d4 << 2];
#pragma unroll
            for (int u = 0; u < 5; u++) {
                float4 u4 = *(const float4*)&uh_s[(tx + 16 * u) * SC_STRIDE + (d4 << 2)];
                acc[u] += v4.x * tanh_fast(w4.x + u4.x);
                acc[u] += v4.y * tanh_fast(w4.y + u4.y);
                acc[u] += v4.z * tanh_fast(w4.z + u4.z);
                acc[u] += v4.w * tanh_fast(w4.w + u4.w);
            }
        }
    }

    int t = t0 + ty;
    if (t < TD) {
        float* arow = g_alignQ + (size_t)quar * BT * SJ + (size_t)(b * TD + t) * SJ;
        int jcol0 = is_src ? jt * 80 : SRCN + (jt - 5) * 80;
#pragma unroll
        for (int u = 0; u < 5; u++)
            arow[jcol0 + tx + 16 * u] = acc[u];
    }
}

// ============================================================
// softmax: combine quarters, hier multiply, mask, softmax
// ============================================================
__global__ __launch_bounds__(256) void softmax_kernel(
    const int* __restrict__ src_len, const int* __restrict__ word_len)
{
    __shared__ float sval[SJ];
    __shared__ float red[256];
    __shared__ float sents[SENTN];
    int row = blockIdx.x, tid = threadIdx.x;
    int b = row / TD;
    if (tid < SENTN) sents[tid] = g_sent[row * SENTN + tid];
    __syncthreads();
    int sl = src_len[b];
    for (int j = tid; j < SJ; j += 256) {
        size_t o = (size_t)row * SJ + j;
        float rv = g_alignQ[o] + g_alignQ[(size_t)BT * SJ + o]
                 + g_alignQ[2 * (size_t)BT * SJ + o] + g_alignQ[3 * (size_t)BT * SJ + o];
        float val;
        if (j < SRCN) {
            val = (j < sl) ? rv : -1e30f;
        } else {
            int jw = j - SRCN; int s = jw / WORDN, w = jw - s * WORDN;
            val = (w < word_len[b * SENTN + s]) ? rv * sents[s] : -1e30f;
        }
        sval[j] = val;
    }
    __syncthreads();
    float m = -3.4e38f;
    for (int j = tid; j < SJ; j += 256) m = fmaxf(m, sval[j]);
    red[tid] = m; __syncthreads();
    for (int o = 128; o; o >>= 1) { if (tid < o) red[tid] = fmaxf(red[tid], red[tid + o]); __syncthreads(); }
    m = red[0]; __syncthreads();
    float s = 0.f;
    for (int j = tid; j < SJ; j += 256) { float e = __expf(sval[j] - m); sval[j] = e; s += e; }
    red[tid] = s; __syncthreads();
    for (int o = 128; o; o >>= 1) { if (tid < o) red[tid] += red[tid + o]; __syncthreads(); }
    float inv = 1.0f / red[0];
    for (int j = tid; j < SJ; j += 256) g_p[(size_t)row * SJ + j] = sval[j] * inv;
}

// ============================================================
// context: c[b,t,d] = sum_j p[b,t,j] * mem[b,j,d]
// ============================================================
__global__ __launch_bounds__(256) void context_kernel(
    const float* __restrict__ srcb, const float* __restrict__ wordb, float* __restrict__ out)
{
    __shared__ float p_s[50 * 80];
    __shared__ float m_s[80 * 33];
    int tid = threadIdx.x;
    int b = blockIdx.y;
    int d0 = blockIdx.x * 32;
    int tx = tid & 31, ty = tid >> 5;
    float acc[7] = {};

    for (int j0 = 0; j0 < SJ; j0 += 80) {
        __syncthreads();
        for (int i = tid; i < 50 * 80; i += 256) {
            int r = i / 80, c = i - r * 80;
            p_s[i] = g_p[(size_t)(b * TD + r) * SJ + j0 + c];
        }
        for (int i = tid; i < 80 * 32; i += 256) {
            int r = i >> 5, c = i & 31;
            int j = j0 + r;
            const float* mp;
            if (j < SRCN) mp = srcb + (size_t)(j * BD + b) * DD;
            else { int jw = j - SRCN; int s = jw / WORDN, w = jw - s * WORDN;
                   mp = wordb + (size_t)((w * BD + b) * SENTN + s) * DD; }
            m_s[r * 33 + c] = mp[d0 + c];
        }
        __syncthreads();
        for (int j = 0; j < 80; j++) {
            float mv = m_s[j * 33 + tx];
#pragma unroll
            for (int q = 0; q < 7; q++) {
                int t = ty + (q << 3);
                if (t < TD) acc[q] += p_s[t * 80 + j] * mv;
            }
        }
    }
#pragma unroll
    for (int q = 0; q < 7; q++) {
        int t = ty + (q << 3);
        if (t < TD) out[(size_t)(b * TD + t) * DD + d0 + tx] = acc[q];
    }
}

// ============================================================
extern "C" void kernel_launch(void* const* d_in, const int* in_sizes, int n_in,
                              void* d_out, int out_size)
{
    const float* source    = (const float*)d_in[0];
    const float* src_bank  = (const float*)d_in[1];
    const int*   src_len   = (const int*)  d_in[2];
    const float* sent_bank = (const float*)d_in[3];
    const float* word_bank = (const float*)d_in[5];
    const int*   word_len  = (const int*)  d_in[6];
    const float* Wq_word = (const float*)d_in[7];
    const float* bq_word = (const float*)d_in[8];
    const float* Uc_word = (const float*)d_in[9];
    const float* v_word  = (const float*)d_in[10];
    const float* Wq_sent = (const float*)d_in[11];
    const float* bq_sent = (const float*)d_in[12];
    const float* Uc_sent = (const float*)d_in[13];
    const float* v_sent  = (const float*)d_in[14];
    const float* Wq_pass = (const float*)d_in[15];
    const float* bq_pass = (const float*)d_in[16];
    const float* Uc_pass = (const float*)d_in[17];
    const float* v_pass  = (const float*)d_in[18];
    float* out = (float*)d_out;

    conv_ab<<<MROWS + 6 * 512, 128>>>(
        sent_bank, src_bank, word_bank, source,
        Uc_sent, Uc_pass, Uc_word, Wq_word, Wq_sent, Wq_pass);
    bf16_gemm<<<dim3(80, 8), 128>>>(bq_word, bq_sent, bq_pass);
    sent_kernel<<<200, 512>>>(v_sent);
    score_kernel<<<dim3(13, 4, 16), 256>>>(v_pass, v_word);
    softmax_kernel<<<200, 256>>>(src_len, word_len);
    context_kernel<<<dim3(16, 4), 256>>>(src_bank, word_bank, out);
}

// round 17
// speedup vs baseline: 1.0925x; 1.0925x over previous
#include <cuda_runtime.h>
#include <cuda_fp16.h>
#include <cstdint>

#define BD 4
#define TD 50
#define DD 512
#define SRCN 400
#define SENTN 16
#define WORDN 40
#define SJ 1040
#define BT 200

#define MROWS 5120
#define ROW_SENT 0
#define ROW_SRC 128
#define ROW_WORD 1792
#define ROW_WQW 4352
#define ROW_WQS 4608
#define ROW_WQP 4864

// ---- scratch (device globals) ----
__device__ __half g_AhiG[MROWS * DD];
__device__ __half g_AloG[MROWS * DD];
__device__ __half g_BhG[6 * DD * DD];          // [set][k][n] single fp16
__device__ float g_act[MROWS * DD];
__device__ float g_alignQ[4 * BT * SJ];        // d-quarter partial scores
__device__ float g_p[BT * SJ];

__device__ __forceinline__ float tanh_fast(float x) {
    float y;
    asm("tanh.approx.f32 %0, %1;" : "=f"(y) : "f"(x));
    return y;
}
__device__ __forceinline__ uint32_t smem_u32(const void* p) {
    uint32_t a;
    asm("{ .reg .u64 t; cvta.to.shared.u64 t, %1; cvt.u32.u64 %0, t; }" : "=r"(a) : "l"(p));
    return a;
}
#define MMA_F16(d, a, b) \
    asm volatile("mma.sync.aligned.m16n8k16.row.col.f32.f16.f16.f32 " \
        "{%0,%1,%2,%3}, {%4,%5,%6,%7}, {%8,%9}, {%0,%1,%2,%3};" \
        : "+f"((d)[0]), "+f"((d)[1]), "+f"((d)[2]), "+f"((d)[3]) \
        : "r"((a)[0]), "r"((a)[1]), "r"((a)[2]), "r"((a)[3]), "r"((b)[0]), "r"((b)[1]))
#define LDSM_X4_T(r, addr) \
    asm volatile("ldmatrix.sync.aligned.m8n8.x4.trans.shared.b16 {%0,%1,%2,%3}, [%4];" \
        : "=r"((r)[0]), "=r"((r)[1]), "=r"((r)[2]), "=r"((r)[3]) : "r"(addr))
#define CP_ASYNC16(saddr, gptr) \
    asm volatile("cp.async.cg.shared.global [%0], [%1], 16;" :: "r"(saddr), "l"(gptr))
#define CP_COMMIT() asm volatile("cp.async.commit_group;" ::: "memory")
#define CP_WAIT1()  asm volatile("cp.async.wait_group 1;" ::: "memory")
#define CP_WAIT0()  asm volatile("cp.async.wait_group 0;" ::: "memory")

__device__ __forceinline__ uint32_t pack_h2(float a, float b) {
    __half2 t = __floats2half2_rn(a, b);
    return *(uint32_t*)&t;
}

// ============================================================
// merged conversion: blocks [0,MROWS) gather+split A rows (fp16 hi/lo);
// blocks [MROWS, MROWS+3072) round the 6 weight matrices to fp16.
// ============================================================
__global__ __launch_bounds__(128) void conv_ab(
    const float* __restrict__ sentb, const float* __restrict__ srcb,
    const float* __restrict__ wordb, const float* __restrict__ source,
    const float* __restrict__ W0, const float* __restrict__ W1, const float* __restrict__ W2,
    const float* __restrict__ W3, const float* __restrict__ W4, const float* __restrict__ W5)
{
    int blk = blockIdx.x;
    if (blk < MROWS) {
        int r = blk;
        const float* p;
        if (r < ROW_SRC) {
            int q = r < 64 ? r : 63; int b = q >> 4, j = q & 15;
            p = sentb + (size_t)(j * BD + b) * DD;
        } else if (r < ROW_WORD) {
            int q = r - ROW_SRC; if (q > 1599) q = 1599;
            int b = q / SRCN, i = q - b * SRCN;
            p = srcb + (size_t)(i * BD + b) * DD;
        } else if (r < ROW_WQW) {
            int q = r - ROW_WORD; int b = q / 640, rem = q - b * 640;
            int s = rem / WORDN, w = rem - s * WORDN;
            p = wordb + (size_t)((w * BD + b) * SENTN + s) * DD;
        } else {
            int q = (r - ROW_WQW) & 255; if (q > BT - 1) q = BT - 1;
            p = source + (size_t)q * DD;
        }
        int d = threadIdx.x * 4;
        float4 x = *(const float4*)(p + d);
        float h0 = __half2float(__float2half_rn(x.x));
        float h1 = __half2float(__float2half_rn(x.y));
        float h2 = __half2float(__float2half_rn(x.z));
        float h3 = __half2float(__float2half_rn(x.w));
        size_t o = (size_t)r * DD + d;
        *(uint2*)&g_AhiG[o] = make_uint2(pack_h2(h0, h1), pack_h2(h2, h3));
        *(uint2*)&g_AloG[o] = make_uint2(pack_h2(x.x - h0, x.y - h1), pack_h2(x.z - h2, x.w - h3));
    } else {
        int g = blk - MROWS;
        int set = g >> 9, k = g & 511;
        const float* W = (set == 0) ? W0 : (set == 1) ? W1 : (set == 2) ? W2 :
                         (set == 3) ? W3 : (set == 4) ? W4 : W5;
        int n = threadIdx.x * 4;
        float4 x = *(const float4*)&W[(size_t)k * DD + n];
        size_t o = (size_t)set * DD * DD + (size_t)k * DD + n;
        *(uint2*)&g_BhG[o] = make_uint2(pack_h2(x.x, x.y), pack_h2(x.z, x.w));
    }
}

// ============================================================
// fp16 2-pass mma GEMM (A split hi/lo, B single), cp.async 2-stage
// CTA tile 64(M) x 64(N), K=512, 128 threads (4 warps, warp 32x32)
// grid (80, 8) = 640 CTAs. smem ~29.7 KB static.
// ============================================================
#define APST 20
#define BST_U 36
#define BSTH 72
#define A_ST (64 * APST)
#define B_ST (32 * BST_U)
#define OFF_AHI(s) ((s) * A_ST)
#define OFF_ALO(s) (2 * A_ST + (s) * A_ST)
#define OFF_BH(s)  (4 * A_ST + (s) * B_ST)
#define SMEM_U     (4 * A_ST + 2 * B_ST)

__device__ __forceinline__ void stage_chunk64(
    uint32_t sb, int st, int kc, int m0, int n0,
    const __half* BhSeg, int tid)
{
    int k0 = kc * 32;
#pragma unroll
    for (int s = 0; s < 2; s++) {
        int g = tid + s * 128;
        int row = g >> 2, c = g & 3;
        size_t go = (size_t)(m0 + row) * DD + k0 + c * 8;
        uint32_t so = 4 * (uint32_t)(row * APST + c * 4);
        CP_ASYNC16(sb + 4 * OFF_AHI(st) + so, g_AhiG + go);
        CP_ASYNC16(sb + 4 * OFF_ALO(st) + so, g_AloG + go);
    }
#pragma unroll
    for (int s = 0; s < 2; s++) {
        int g = tid + s * 128;
        int k = g >> 3, c = g & 7;
        size_t go = (size_t)(k0 + k) * DD + n0 + c * 8;
        uint32_t so = 4 * (uint32_t)(k * BST_U + c * 4);
        CP_ASYNC16(sb + 4 * OFF_BH(st) + so, BhSeg + go);
    }
}

__global__ __launch_bounds__(128, 6) void f16_gemm(
    const float* __restrict__ bqw, const float* __restrict__ bqs, const float* __restrict__ bqp)
{
    __shared__ __align__(16) uint32_t smU[SMEM_U];
    uint32_t sb = smem_u32(smU);

    int tid = threadIdx.x, lane = tid & 31, wid = tid >> 5;
    int m0 = blockIdx.x * 64, n0 = blockIdx.y * 64;
    int seg = (m0 < ROW_SRC) ? 0 : (m0 < ROW_WORD) ? 1 : (m0 < ROW_WQW) ? 2 :
              (m0 < ROW_WQS) ? 3 : (m0 < ROW_WQP) ? 4 : 5;
    const __half* BhSeg = g_BhG + (size_t)seg * DD * DD;

    int wm = (wid & 1) * 32, wn = (wid >> 1) * 32;
    int gr = lane >> 2, gc = lane & 3;
    int quad = lane >> 3, lrow = lane & 7;
    int ldsm_half = ((quad & 1) * 8 + lrow) * BSTH + (quad >> 1) * 8 + wn;

    float acc[2][4][4];
#pragma unroll
    for (int mt = 0; mt < 2; mt++)
#pragma unroll
        for (int nt = 0; nt < 4; nt++)
#pragma unroll
            for (int c = 0; c < 4; c++) acc[mt][nt][c] = 0.0f;

    stage_chunk64(sb, 0, 0, m0, n0, BhSeg, tid);
    CP_COMMIT();

    for (int kc = 0; kc < 16; kc++) {
        int st = kc & 1;
        if (kc < 15) {
            stage_chunk64(sb, st ^ 1, kc + 1, m0, n0, BhSeg, tid);
            CP_COMMIT();
            CP_WAIT1();
        } else {
            CP_WAIT0();
        }
        __syncthreads();

#pragma unroll
        for (int step = 0; step < 2; step++) {
            int kkp = step * 8;
            int kk2 = step * 16;
            uint32_t ah[2][4], al[2][4];
#pragma unroll
            for (int mt = 0; mt < 2; mt++) {
                int mr = wm + mt * 16 + gr;
                ah[mt][0] = smU[OFF_AHI(st) + mr * APST + kkp + gc];
                ah[mt][1] = smU[OFF_AHI(st) + (mr + 8) * APST + kkp + gc];
                ah[mt][2] = smU[OFF_AHI(st) + mr * APST + kkp + gc + 4];
                ah[mt][3] = smU[OFF_AHI(st) + (mr + 8) * APST + kkp + gc + 4];
                al[mt][0] = smU[OFF_ALO(st) + mr * APST + kkp + gc];
                al[mt][1] = smU[OFF_ALO(st) + (mr + 8) * APST + kkp + gc];
                al[mt][2] = smU[OFF_ALO(st) + mr * APST + kkp + gc + 4];
                al[mt][3] = smU[OFF_ALO(st) + (mr + 8) * APST + kkp + gc + 4];
            }
#pragma unroll
            for (int np = 0; np < 2; np++) {
                uint32_t hoff = (uint32_t)((kk2 * BSTH + np * 16 + ldsm_half) * 2);
                uint32_t bh4[4];
                LDSM_X4_T(bh4, sb + 4 * OFF_BH(st) + hoff);
#pragma unroll
                for (int sub = 0; sub < 2; sub++) {
#pragma unroll
                    for (int mt = 0; mt < 2; mt++) {
                        MMA_F16(acc[mt][np * 2 + sub], ah[mt], &bh4[sub * 2]);
                        MMA_F16(acc[mt][np * 2 + sub], al[mt], &bh4[sub * 2]);
                    }
                }
            }
        }
        __syncthreads();
    }

    const float* bias = (seg == 3) ? bqw : (seg == 4) ? bqs : (seg == 5) ? bqp : (const float*)0;
#pragma unroll
    for (int nt = 0; nt < 4; nt++) {
        int n = n0 + wn + nt * 8 + gc * 2;
        float b0 = bias ? bias[n] : 0.0f;
        float b1 = bias ? bias[n + 1] : 0.0f;
#pragma unroll
        for (int mt = 0; mt < 2; mt++) {
            int m = m0 + wm + mt * 16 + gr;
            *(float2*)&g_act[(size_t)m * DD + n] =
                make_float2(acc[mt][nt][0] + b0, acc[mt][nt][1] + b1);
            *(float2*)&g_act[(size_t)(m + 8) * DD + n] =
                make_float2(acc[mt][nt][2] + b0, acc[mt][nt][3] + b1);
        }
    }
}

// ============================================================
// main score kernel: 2t x 5j per thread, d quarters
// grid (13 j-tiles, 2 t-tiles of 32, 16 = b + 4*quar), 256 threads
// ============================================================
#define SC_STRIDE 68
__global__ __launch_bounds__(256) void score_kernel(
    const float* __restrict__ v_pass, const float* __restrict__ v_word)
{
    __shared__ float wq_s[32 * SC_STRIDE];
    __shared__ float uh_s[80 * SC_STRIDE];
    __shared__ float v_s[64];
    int tid = threadIdx.x;
    int jt = blockIdx.x, tt = blockIdx.y;
    int b = blockIdx.z & 3, quar = blockIdx.z >> 2;
    int t0 = tt * 32;
    bool is_src = (jt < 5);
    const float* wqb = g_act + (size_t)((is_src ? ROW_WQP : ROW_WQW) + b * TD) * DD;
    int uh0 = is_src ? (ROW_SRC + b * SRCN + jt * 80) : (ROW_WORD + b * 640 + (jt - 5) * 80);
    const float* v = is_src ? v_pass : v_word;
    int d_base = quar * 128;

    int tx = tid & 15, ty = tid >> 4;
    float acc[2][5] = {};

    for (int c = 0; c < 2; c++) {
        int d0 = d_base + c * 64;
        __syncthreads();
        for (int i = tid; i < 32 * 16; i += 256) {
            int r = i >> 4, col = (i & 15) << 2;
            *(float4*)&wq_s[r * SC_STRIDE + col] =
                *(const float4*)&wqb[(size_t)(t0 + r) * DD + d0 + col];
        }
        for (int i = tid; i < 80 * 16; i += 256) {
            int r = i >> 4, col = (i & 15) << 2;
            *(float4*)&uh_s[r * SC_STRIDE + col] =
                *(const float4*)&g_act[(size_t)(uh0 + r) * DD + d0 + col];
        }
        if (tid < 64) v_s[tid] = v[d0 + tid];
        __syncthreads();
#pragma unroll 4
        for (int d4 = 0; d4 < 16; d4++) {
            float4 wa = *(const float4*)&wq_s[ty * SC_STRIDE + (d4 << 2)];
            float4 wb = *(const float4*)&wq_s[(ty + 16) * SC_STRIDE + (d4 << 2)];
            float4 v4 = *(const float4*)&v_s[d4 << 2];
#pragma unroll
            for (int u = 0; u < 5; u++) {
                float4 u4 = *(const float4*)&uh_s[(tx + 16 * u) * SC_STRIDE + (d4 << 2)];
                acc[0][u] += v4.x * tanh_fast(wa.x + u4.x);
                acc[0][u] += v4.y * tanh_fast(wa.y + u4.y);
                acc[0][u] += v4.z * tanh_fast(wa.z + u4.z);
                acc[0][u] += v4.w * tanh_fast(wa.w + u4.w);
                acc[1][u] += v4.x * tanh_fast(wb.x + u4.x);
                acc[1][u] += v4.y * tanh_fast(wb.y + u4.y);
                acc[1][u] += v4.z * tanh_fast(wb.z + u4.z);
                acc[1][u] += v4.w * tanh_fast(wb.w + u4.w);
            }
        }
    }

    int jcol0 = is_src ? jt * 80 : SRCN + (jt - 5) * 80;
#pragma unroll
    for (int h = 0; h < 2; h++) {
        int t = t0 + ty + h * 16;
        if (t < TD) {
            float* arow = g_alignQ + (size_t)quar * BT * SJ + (size_t)(b * TD + t) * SJ;
#pragma unroll
            for (int u = 0; u < 5; u++)
                arow[jcol0 + tx + 16 * u] = acc[h][u];
        }
    }
}

// ============================================================
// softmax: fused sentence scores + combine quarters + hier + mask + softmax
// ============================================================
__global__ __launch_bounds__(256) void softmax_kernel(
    const int* __restrict__ src_len, const int* __restrict__ word_len,
    const float* __restrict__ v_sent)
{
    __shared__ float sval[SJ];
    __shared__ float red[256];
    __shared__ float sents[SENTN];
    int row = blockIdx.x, tid = threadIdx.x;
    int b = row / TD;

    // fused sentence scores: 16 j-groups x 16 lanes
    {
        int jg = tid >> 4, l16 = tid & 15;
        const float* wq = g_act + (size_t)(ROW_WQS + row) * DD;
        const float* uh = g_act + (size_t)(b * 16 + jg) * DD;
        float a = 0.f;
#pragma unroll
        for (int it = 0; it < 8; it++) {
            int d = it * 64 + l16 * 4;
            float4 wv = *(const float4*)&wq[d];
            float4 uv = *(const float4*)&uh[d];
            float4 vv = *(const float4*)&v_sent[d];
            a += vv.x * tanh_fast(wv.x + uv.x);
            a += vv.y * tanh_fast(wv.y + uv.y);
            a += vv.z * tanh_fast(wv.z + uv.z);
            a += vv.w * tanh_fast(wv.w + uv.w);
        }
#pragma unroll
        for (int o = 8; o; o >>= 1) a += __shfl_xor_sync(0xffffffffu, a, o, 16);
        if (l16 == 0) sents[jg] = a;
    }
    __syncthreads();

    int sl = src_len[b];
    for (int j = tid; j < SJ; j += 256) {
        size_t o = (size_t)row * SJ + j;
        float rv = g_alignQ[o] + g_alignQ[(size_t)BT * SJ + o]
                 + g_alignQ[2 * (size_t)BT * SJ + o] + g_alignQ[3 * (size_t)BT * SJ + o];
        float val;
        if (j < SRCN) {
            val = (j < sl) ? rv : -1e30f;
        } else {
            int jw = j - SRCN; int s = jw / WORDN, w = jw - s * WORDN;
            val = (w < word_len[b * SENTN + s]) ? rv * sents[s] : -1e30f;
        }
        sval[j] = val;
    }
    __syncthreads();
    float m = -3.4e38f;
    for (int j = tid; j < SJ; j += 256) m = fmaxf(m, sval[j]);
    red[tid] = m; __syncthreads();
    for (int o = 128; o; o >>= 1) { if (tid < o) red[tid] = fmaxf(red[tid], red[tid + o]); __syncthreads(); }
    m = red[0]; __syncthreads();
    float s = 0.f;
    for (int j = tid; j < SJ; j += 256) { float e = __expf(sval[j] - m); sval[j] = e; s += e; }
    red[tid] = s; __syncthreads();
    for (int o = 128; o; o >>= 1) { if (tid < o) red[tid] += red[tid + o]; __syncthreads(); }
    float inv = 1.0f / red[0];
    for (int j = tid; j < SJ; j += 256) g_p[(size_t)row * SJ + j] = sval[j] * inv;
}

// ============================================================
// context: c[b,t,d] = sum_j p[b,t,j] * mem[b,j,d]
// ============================================================
__global__ __launch_bounds__(256) void context_kernel(
    const float* __restrict__ srcb, const float* __restrict__ wordb, float* __restrict__ out)
{
    __shared__ float p_s[50 * 80];
    __shared__ float m_s[80 * 33];
    int tid = threadIdx.x;
    int b = blockIdx.y;
    int d0 = blockIdx.x * 32;
    int tx = tid & 31, ty = tid >> 5;
    float acc[7] = {};

    for (int j0 = 0; j0 < SJ; j0 += 80) {
        __syncthreads();
        for (int i = tid; i < 50 * 80; i += 256) {
            int r = i / 80, c = i - r * 80;
            p_s[i] = g_p[(size_t)(b * TD + r) * SJ + j0 + c];
        }
        for (int i = tid; i < 80 * 32; i += 256) {
            int r = i >> 5, c = i & 31;
            int j = j0 + r;
            const float* mp;
            if (j < SRCN) mp = srcb + (size_t)(j * BD + b) * DD;
            else { int jw = j - SRCN; int s = jw / WORDN, w = jw - s * WORDN;
                   mp = wordb + (size_t)((w * BD + b) * SENTN + s) * DD; }
            m_s[r * 33 + c] = mp[d0 + c];
        }
        __syncthreads();
        for (int j = 0; j < 80; j++) {
            float mv = m_s[j * 33 + tx];
#pragma unroll
            for (int q = 0; q < 7; q++) {
                int t = ty + (q << 3);
                if (t < TD) acc[q] += p_s[t * 80 + j] * mv;
            }
        }
    }
#pragma unroll
    for (int q = 0; q < 7; q++) {
        int t = ty + (q << 3);
        if (t < TD) out[(size_t)(b * TD + t) * DD + d0 + tx] = acc[q];
    }
}

// ============================================================
extern "C" void kernel_launch(void* const* d_in, const int* in_sizes, int n_in,
                              void* d_out, int out_size)
{
    const float* source    = (const float*)d_in[0];
    const float* src_bank  = (const float*)d_in[1];
    const int*   src_len   = (const int*)  d_in[2];
    const float* sent_bank = (const float*)d_in[3];
    const float* word_bank = (const float*)d_in[5];
    const int*   word_len  = (const int*)  d_in[6];
    const float* Wq_word = (const float*)d_in[7];
    const float* bq_word = (const float*)d_in[8];
    const float* Uc_word = (const float*)d_in[9];
    const float* v_word  = (const float*)d_in[10];
    const float* Wq_sent = (const float*)d_in[11];
    const float* bq_sent = (const float*)d_in[12];
    const float* Uc_sent = (const float*)d_in[13];
    const float* v_sent  = (const float*)d_in[14];
    const float* Wq_pass = (const float*)d_in[15];
    const float* bq_pass = (const float*)d_in[16];
    const float* Uc_pass = (const float*)d_in[17];
    const float* v_pass  = (const float*)d_in[18];
    float* out = (float*)d_out;

    conv_ab<<<MROWS + 6 * 512, 128>>>(
        sent_bank, src_bank, word_bank, source,
        Uc_sent, Uc_pass, Uc_word, Wq_word, Wq_sent, Wq_pass);
    f16_gemm<<<dim3(80, 8), 128>>>(bq_word, bq_sent, bq_pass);
    score_kernel<<<dim3(13, 2, 16), 256>>>(v_pass, v_word);
    softmax_kernel<<<200, 256>>>(src_len, word_len, v_sent);
    context_kernel<<<dim3(16, 4), 256>>>(src_bank, word_bank, out);
}